// round 15
// baseline (speedup 1.0000x reference)
#include <cuda_runtime.h>
#include <cuda_bf16.h>
#include <math.h>
#include <stdint.h>

#define BATCH 4
#define NPTS 4096
#define NPTS2 4096
#define CINC 128
#define DIMC 64
#define KNNC 20
#define UPF 2
#define HPOSC 64
#define HATTC 256
#define EPSV 1e-5f
#define PPB 2
#define ABF_STRIDE 264   // channels stride in s_abf rows
#define HBF_STRIDE 72    // o stride in s_hbf / s_pe1bf rows

// ---------------- scratch ----------------
__device__ float g_qt[BATCH * NPTS * DIMC];
__device__ float g_kt[BATCH * NPTS2 * DIMC];
__device__ float g_vt[BATCH * NPTS2 * DIMC];
__device__ int   g_idx[BATCH * NPTS * KNNC];
__device__ float g_wqt[CINC * DIMC];
__device__ float g_wkt[CINC * DIMC];
__device__ float g_wvt[CINC * DIMC];
__device__ unsigned g_w2frag[2 * 8 * 16 * 32 * 4];
__device__ unsigned g_w1frag[2 * 16 * 4 * 32 * 4];
__device__ unsigned g_pwfrag[2 * 4 * 4 * 32 * 4];
__device__ float g_c1inv[HATTC];
__device__ float g_c1bias[HATTC];
__device__ float g_pw1s[HPOSC * 3];   // pw1 prescaled by BN inv
__device__ float g_pbias[HPOSC];      // fused BN bias for pos layer 1

// ---------------- f32x2 helpers ----------------
__device__ __forceinline__ unsigned long long ffma2(
    unsigned long long a, unsigned long long b, unsigned long long c) {
    unsigned long long d;
    asm("fma.rn.f32x2 %0, %1, %2, %3;" : "=l"(d) : "l"(a), "l"(b), "l"(c));
    return d;
}
__device__ __forceinline__ unsigned long long pack2(float lo, float hi) {
    unsigned long long d;
    asm("mov.b64 %0, {%1, %2};" : "=l"(d) : "f"(lo), "f"(hi));
    return d;
}
__device__ __forceinline__ void unpack2(unsigned long long v, float& lo, float& hi) {
    asm("mov.b64 {%0, %1}, %2;" : "=f"(lo), "=f"(hi) : "l"(v));
}

// ---------------- mma.sync helper ----------------
__device__ __forceinline__ void mma16816(float* c, const uint4& a, unsigned b0, unsigned b1) {
    asm volatile(
        "mma.sync.aligned.m16n8k16.row.col.f32.bf16.bf16.f32 "
        "{%0,%1,%2,%3}, {%4,%5,%6,%7}, {%8,%9}, {%0,%1,%2,%3};"
        : "+f"(c[0]), "+f"(c[1]), "+f"(c[2]), "+f"(c[3])
        : "r"(a.x), "r"(a.y), "r"(a.z), "r"(a.w), "r"(b0), "r"(b1));
}
__device__ __forceinline__ unsigned bfpack(float x0, float x1) {
    return (unsigned)__bfloat16_as_ushort(__float2bfloat16_rn(x0)) |
           ((unsigned)__bfloat16_as_ushort(__float2bfloat16_rn(x1)) << 16);
}

// ================= prep =================
__global__ __launch_bounds__(256) void prep_kernel(
    const float* __restrict__ aw1, const float* __restrict__ pw2,
    const float* __restrict__ wq, const float* __restrict__ wk,
    const float* __restrict__ wv, const float* __restrict__ awt,
    const float* __restrict__ ab1, const float* __restrict__ ag,
    const float* __restrict__ abt2, const float* __restrict__ am,
    const float* __restrict__ av,
    const float* __restrict__ pw1, const float* __restrict__ pb1,
    const float* __restrict__ pg,  const float* __restrict__ pbt,
    const float* __restrict__ pm,  const float* __restrict__ pv)
{
    int i = blockIdx.x * 256 + threadIdx.x;
    if (i < DIMC * CINC) {
        int o = i >> 7, c = i & 127;
        g_wqt[c * DIMC + o] = wq[i];
        g_wkt[c * DIMC + o] = wk[i];
        g_wvt[c * DIMC + o] = wv[i];
    }
    if (i < HATTC) {
        float inv = ag[i] * rsqrtf(av[i] + EPSV);
        g_c1inv[i] = inv;
        g_c1bias[i] = fmaf(ab1[i], inv, abt2[i]) - am[i] * inv;
    }
    if (i < HPOSC) {
        float inv = pg[i] * rsqrtf(pv[i] + EPSV);
        g_pbias[i] = (pb1[i] - pm[i]) * inv + pbt[i];
        g_pw1s[i * 3 + 0] = pw1[i * 3 + 0] * inv;
        g_pw1s[i * 3 + 1] = pw1[i * 3 + 1] * inv;
        g_pw1s[i * 3 + 2] = pw1[i * 3 + 2] * inv;
    }
    if (i < 32768) {                       // W2 A-fragments
        int reg = i & 3, lane = (i >> 2) & 31, ks = (i >> 7) & 15;
        int mt = (i >> 11) & 7, plane = (i >> 14) & 1;
        int gr = lane >> 2, gc = lane & 3;
        int row = mt * 16 + gr + (reg & 1) * 8;
        int col = ks * 16 + 2 * gc + ((reg >> 1) & 1) * 8;
        float x0 = awt[col * 128 + row];
        float x1 = awt[(col + 1) * 128 + row];
        unsigned v;
        if (plane == 0) v = bfpack(x0, x1);
        else {
            float h0 = __bfloat162float(__float2bfloat16_rn(x0));
            float h1 = __bfloat162float(__float2bfloat16_rn(x1));
            v = bfpack(x0 - h0, x1 - h1);
        }
        g_w2frag[i] = v;
    }
    if (i < 16384) {                       // W1 A-fragments
        int reg = i & 3, lane = (i >> 2) & 31, ks = (i >> 7) & 3;
        int mt = (i >> 9) & 15, plane = (i >> 13) & 1;
        int gr = lane >> 2, gc = lane & 3;
        int row = mt * 16 + gr + (reg & 1) * 8;
        int col = ks * 16 + 2 * gc + ((reg >> 1) & 1) * 8;
        float x0 = aw1[row * DIMC + col];
        float x1 = aw1[row * DIMC + col + 1];
        unsigned v;
        if (plane == 0) v = bfpack(x0, x1);
        else {
            float h0 = __bfloat162float(__float2bfloat16_rn(x0));
            float h1 = __bfloat162float(__float2bfloat16_rn(x1));
            v = bfpack(x0 - h0, x1 - h1);
        }
        g_w1frag[i] = v;
    }
    if (i < 4096) {                        // PW2 A-fragments
        int reg = i & 3, lane = (i >> 2) & 31, ks = (i >> 7) & 3;
        int mt = (i >> 9) & 3, plane = (i >> 11) & 1;
        int gr = lane >> 2, gc = lane & 3;
        int row = mt * 16 + gr + (reg & 1) * 8;
        int col = ks * 16 + 2 * gc + ((reg >> 1) & 1) * 8;
        float x0 = pw2[row * HPOSC + col];
        float x1 = pw2[row * HPOSC + col + 1];
        unsigned v;
        if (plane == 0) v = bfpack(x0, x1);
        else {
            float h0 = __bfloat162float(__float2bfloat16_rn(x0));
            float h1 = __bfloat162float(__float2bfloat16_rn(x1));
            v = bfpack(x0 - h0, x1 - h1);
        }
        g_pwfrag[i] = v;
    }
}

// ================= QKV: 64 points per block (256 blocks -> full wave fill) =================
__global__ __launch_bounds__(256) void qkv_kernel(
    const float* __restrict__ query, const float* __restrict__ key_feat,
    const float* __restrict__ bq, const float* __restrict__ bk, const float* __restrict__ bv)
{
    int b = blockIdx.y;
    int n0 = blockIdx.x * 64;
    int tid = threadIdx.x;
    __shared__ __align__(16) float tile[CINC * 64];   // 32 KB
    int o = tid & 63, jb = tid >> 6;                  // jb: 0..3 -> points jb*16 .. jb*16+15

    for (int i = tid; i < CINC * 64; i += 256) {
        int c = i >> 6, j = i & 63;
        tile[i] = query[(b * CINC + c) * NPTS + n0 + j];
    }
    __syncthreads();
    {
        unsigned long long acc[8];
#pragma unroll
        for (int m = 0; m < 8; m++) acc[m] = 0ULL;
#pragma unroll 4
        for (int c = 0; c < CINC; c++) {
            float w = g_wqt[c * DIMC + o];
            unsigned long long wp = pack2(w, w);
            const ulonglong2* tp = reinterpret_cast<const ulonglong2*>(tile + c * 64 + jb * 16);
#pragma unroll
            for (int jj = 0; jj < 4; jj++) {
                ulonglong2 t = tp[jj];
                acc[2 * jj]     = ffma2(wp, t.x, acc[2 * jj]);
                acc[2 * jj + 1] = ffma2(wp, t.y, acc[2 * jj + 1]);
            }
        }
        float bias = bq[o];
#pragma unroll
        for (int m = 0; m < 8; m++) {
            float lo, hi;
            unpack2(acc[m], lo, hi);
            int j = jb * 16 + 2 * m;
            g_qt[(b * NPTS + n0 + j) * DIMC + o]     = lo + bias;
            g_qt[(b * NPTS + n0 + j + 1) * DIMC + o] = hi + bias;
        }
    }
    __syncthreads();
    for (int i = tid; i < CINC * 64; i += 256) {
        int c = i >> 6, j = i & 63;
        tile[i] = key_feat[(b * CINC + c) * NPTS2 + n0 + j];
    }
    __syncthreads();
#pragma unroll
    for (int which = 0; which < 2; which++) {
        const float* wt = which ? g_wvt : g_wkt;
        float* gout = which ? g_vt : g_kt;
        float bias = which ? bv[o] : bk[o];
        unsigned long long acc[8];
#pragma unroll
        for (int m = 0; m < 8; m++) acc[m] = 0ULL;
#pragma unroll 4
        for (int c = 0; c < CINC; c++) {
            float w = wt[c * DIMC + o];
            unsigned long long wp = pack2(w, w);
            const ulonglong2* tp = reinterpret_cast<const ulonglong2*>(tile + c * 64 + jb * 16);
#pragma unroll
            for (int jj = 0; jj < 4; jj++) {
                ulonglong2 t = tp[jj];
                acc[2 * jj]     = ffma2(wp, t.x, acc[2 * jj]);
                acc[2 * jj + 1] = ffma2(wp, t.y, acc[2 * jj + 1]);
            }
        }
#pragma unroll
        for (int m = 0; m < 8; m++) {
            float lo, hi;
            unpack2(acc[m], lo, hi);
            int j = jb * 16 + 2 * m;
            gout[(b * NPTS2 + n0 + j) * DIMC + o]     = lo + bias;
            gout[(b * NPTS2 + n0 + j + 1) * DIMC + o] = hi + bias;
        }
    }
}

// ================= KNN =================
#define INSERT_CHAIN(d_, i_) do { \
    float cd = (d_); int ci = (i_); \
    _Pragma("unroll") \
    for (int j = 0; j < KNNC; j++) { \
        if (cd < bd[j]) { \
            float td = bd[j]; bd[j] = cd; cd = td; \
            int ti = bi[j]; bi[j] = ci; ci = ti; \
        } \
    } \
} while (0)

__global__ __launch_bounds__(512) void knn_kernel(
    const float* __restrict__ pos1, const float* __restrict__ pos2)
{
    int b = blockIdx.y;
    int tid = threadIdx.x;
    int q = tid & 127, quarter = tid >> 7;
    int n = blockIdx.x * 128 + q;

    __shared__ float sx[4096], sy[4096], sz[4096], sq2[4096];  // 64 KB
    __shared__ float smd[512][KNNC];                           // 40 KB
    __shared__ int   smi[512][KNNC];                           // 40 KB
    __shared__ float sbd[512][13];                             // 26 KB
    __shared__ int   sbi[512][13];                             // 26 KB

    for (int i = tid; i < 4096; i += 512) {
        float x = pos2[(b * 3 + 0) * NPTS2 + i];
        float y = pos2[(b * 3 + 1) * NPTS2 + i];
        float z = pos2[(b * 3 + 2) * NPTS2 + i];
        sx[i] = x; sy[i] = y; sz[i] = z;
        sq2[i] = x * x + y * y + z * z;
    }
    float qx = pos1[(b * 3 + 0) * NPTS + n];
    float qy = pos1[(b * 3 + 1) * NPTS + n];
    float qz = pos1[(b * 3 + 2) * NPTS + n];
    float n1 = qx * qx + qy * qy + qz * qz;

    float bd[KNNC];
    int bi[KNNC];
#pragma unroll
    for (int j = 0; j < KNNC; j++) { bd[j] = 3.4e38f; bi[j] = 0; }
    __syncthreads();
    int base = quarter * 1024;

    for (int m = 0; m < 64; m++) {
        int mm = base + m;
        float dot = fmaf(qx, sx[mm], fmaf(qy, sy[mm], qz * sz[mm]));
        float d = n1 + sq2[mm] - 2.f * dot;
        if (d < bd[KNNC - 1]) INSERT_CHAIN(d, mm);
    }
    for (int chunk = 0; chunk < 15; chunk++) {
        int s0 = 64 + chunk * 64;
        float thr = bd[KNNC - 1];
        int cnt = 0;
        for (int m = s0; m < s0 + 64; m++) {
            int mm = base + m;
            float dot = fmaf(qx, sx[mm], fmaf(qy, sy[mm], qz * sz[mm]));
            float d = n1 + sq2[mm] - 2.f * dot;
            if (d < thr) {
                if (cnt < 13) { sbd[tid][cnt] = d; sbi[tid][cnt] = mm; cnt++; }
                else if (d < bd[KNNC - 1]) INSERT_CHAIN(d, mm);
            }
        }
        for (int t = 0; t < cnt; t++) {
            float d = sbd[tid][t];
            int mm = sbi[tid][t];
            if (d < bd[KNNC - 1]) INSERT_CHAIN(d, mm);
        }
    }
#pragma unroll
    for (int j = 0; j < KNNC; j++) { smd[tid][j] = bd[j]; smi[tid][j] = bi[j]; }
    __syncthreads();
    if (quarter == 0) {
        int head[4] = {0, 0, 0, 0};
#pragma unroll
        for (int t = 0; t < KNNC; t++) {
            float best = 3.5e38f;
            int bqv = 0;
#pragma unroll
            for (int qu = 0; qu < 4; qu++) {
                if (head[qu] < KNNC) {
                    float v = smd[qu * 128 + q][head[qu]];
                    if (v < best) { best = v; bqv = qu; }
                }
            }
            g_idx[(b * NPTS + n) * KNNC + t] = smi[bqv * 128 + q][head[bqv]];
            head[bqv]++;
        }
    }
}

// ================= fused attention kernel =================
__global__ __launch_bounds__(256, 4) void attn_kernel(
    const float* __restrict__ pos1, const float* __restrict__ pos2,
    const float* __restrict__ query,
    const float* __restrict__ pb2,
    const float* __restrict__ abt,
    const float* __restrict__ we,  const float* __restrict__ be,
    float* __restrict__ out)
{
    int b = blockIdx.y;
    int n0 = blockIdx.x * PPB;
    int tid = threadIdx.x;

    __shared__ __align__(16) float s_h[PPB * DIMC * KNNC];
    __shared__ __align__(16) float s_vg[PPB * DIMC * KNNC];
    __shared__ __align__(16) unsigned char s_big[PPB * 24 * ABF_STRIDE * 2];
    __shared__ __align__(16) __nv_bfloat16 s_hbf[PPB * 24 * HBF_STRIDE];
    __shared__ float s_q[PPB * DIMC];
    __shared__ float s_prel[PPB * 3 * KNNC];
    __shared__ __align__(16) float s_agg[PPB * DIMC * UPF];   // [p][rr*64+o]
    __shared__ int   s_idx[PPB * KNNC];

    __nv_bfloat16* s_pe1bf = reinterpret_cast<__nv_bfloat16*>(s_big);
    __nv_bfloat16* s_abf = reinterpret_cast<__nv_bfloat16*>(s_big);

    // ---- Phase 0 ----
    if (tid < PPB * KNNC) {
        int p = tid / KNNC, k = tid - p * KNNC;
        s_idx[tid] = g_idx[(b * NPTS + n0 + p) * KNNC + k];
    }
    if (tid < PPB * DIMC) {
        int p = tid >> 6, o = tid & 63;
        s_q[tid] = g_qt[(b * NPTS + n0 + p) * DIMC + o];
    }
    {
        unsigned* hz = reinterpret_cast<unsigned*>(s_hbf);
        for (int e = tid; e < PPB * 4 * (HBF_STRIDE / 2); e += 256) {
            int woff = e % (HBF_STRIDE / 2);
            int rsel = e / (HBF_STRIDE / 2);
            int r = rsel & 3, p = rsel >> 2;
            hz[(p * 24 + 20 + r) * (HBF_STRIDE / 2) + woff] = 0u;
        }
    }
    __syncthreads();
    if (tid < PPB * 3 * KNNC) {
        int p = tid / (3 * KNNC), rem = tid - p * 3 * KNNC;
        int c = rem / KNNC, k = rem - c * KNNC;
        s_prel[tid] = pos1[(b * 3 + c) * NPTS + n0 + p]
                    - pos2[(b * 3 + c) * NPTS2 + s_idx[p * KNNC + k]];
    }
#pragma unroll
    for (int p = 0; p < PPB; p++) {
        for (int e = tid; e < DIMC * KNNC / 4; e += 256) {   // 320 float4 groups
            int k = e >> 4, o4 = e & 15;
            int m = s_idx[p * KNNC + k];
            const float4 kv = *reinterpret_cast<const float4*>(
                g_kt + ((size_t)(b * NPTS2 + m)) * DIMC + o4 * 4);
            const float4 vv = *reinterpret_cast<const float4*>(
                g_vt + ((size_t)(b * NPTS2 + m)) * DIMC + o4 * 4);
            const float4 qv = *reinterpret_cast<const float4*>(s_q + p * DIMC + o4 * 4);
            float* hb = s_h + p * DIMC * KNNC;
            float* vb = s_vg + p * DIMC * KNNC;
            int o = o4 * 4;
            hb[(o + 0) * KNNC + k] = qv.x - kv.x;
            hb[(o + 1) * KNNC + k] = qv.y - kv.y;
            hb[(o + 2) * KNNC + k] = qv.z - kv.z;
            hb[(o + 3) * KNNC + k] = qv.w - kv.w;
            vb[(o + 0) * KNNC + k] = vv.x;
            vb[(o + 1) * KNNC + k] = vv.y;
            vb[(o + 2) * KNNC + k] = vv.z;
            vb[(o + 3) * KNNC + k] = vv.w;
        }
    }
    __syncthreads();

    // ---- Phase 1: pe1 = relu(pw1s @ prel + pbias) -> s_pe1bf bf16 [k][h] ----
    for (int e = tid; e < PPB * 24 * 32; e += 256) {
        int hp = e & 31;
        int rem = e >> 5;
        int k = rem % 24, p = rem / 24;
        float v0 = 0.f, v1 = 0.f;
        if (k < KNNC) {
            const float* pr = s_prel + p * 3 * KNNC;
            float x = pr[k], y = pr[KNNC + k], z = pr[2 * KNNC + k];
            int h0 = 2 * hp, h1 = 2 * hp + 1;
            v0 = fmaxf(fmaf(g_pw1s[h0 * 3], x,
                       fmaf(g_pw1s[h0 * 3 + 1], y,
                       fmaf(g_pw1s[h0 * 3 + 2], z, g_pbias[h0]))), 0.f);
            v1 = fmaxf(fmaf(g_pw1s[h1 * 3], x,
                       fmaf(g_pw1s[h1 * 3 + 1], y,
                       fmaf(g_pw1s[h1 * 3 + 2], z, g_pbias[h1]))), 0.f);
        }
        unsigned* w0 = reinterpret_cast<unsigned*>(s_pe1bf);
        w0[(p * 24 + k) * (HBF_STRIDE / 2) + hp] = bfpack(v0, v1);
    }
    __syncthreads();

    // ---- Phase 1b: pe = pw2 @ pe1 (2-term mma); fold into s_hbf and s_vg ----
    int w = tid >> 5, lane = tid & 31;
    int gr = lane >> 2, gc = lane & 3;
    {
        int p1 = w >> 2, mt = w & 3;
        float Cpe[3][4];
#pragma unroll
        for (int nt = 0; nt < 3; nt++)
#pragma unroll
            for (int r = 0; r < 4; r++) Cpe[nt][r] = 0.f;
        const uint4* PW = reinterpret_cast<const uint4*>(g_pwfrag);
#pragma unroll
        for (int ks = 0; ks < 4; ks++) {
            uint4 Ah = PW[((0 * 4 + mt) * 4 + ks) * 32 + lane];
            uint4 Al = PW[((1 * 4 + mt) * 4 + ks) * 32 + lane];
#pragma unroll
            for (int nt = 0; nt < 3; nt++) {
                const __nv_bfloat16* bh =
                    s_pe1bf + (p1 * 24 + nt * 8 + gr) * HBF_STRIDE + ks * 16 + 2 * gc;
                unsigned b0 = *reinterpret_cast<const unsigned*>(bh);
                unsigned b1 = *reinterpret_cast<const unsigned*>(bh + 8);
                mma16816(Cpe[nt], Ah, b0, b1);
                mma16816(Cpe[nt], Al, b0, b1);
            }
        }
#pragma unroll
        for (int nt = 0; nt < 3; nt++) {
#pragma unroll
            for (int i = 0; i < 2; i++) {
#pragma unroll
                for (int j = 0; j < 2; j++) {
                    int row = mt * 16 + gr + i * 8;
                    int nb = nt * 8 + 2 * gc + j;
                    if (nb < KNNC) {
                        float val = Cpe[nt][i * 2 + j] + pb2[row];
                        int off = p1 * DIMC * KNNC + row * KNNC + nb;
                        float hv = s_h[off] + val;
                        s_vg[off] += val;
                        s_hbf[(p1 * 24 + nb) * HBF_STRIDE + row] = __float2bfloat16_rn(hv);
                    }
                }
            }
        }
    }
    __syncthreads();

    // ---- Phase 2: GEMM1 (2-term mma) both points -> s_abf ----
    const uint4* W1 = reinterpret_cast<const uint4*>(g_w1frag);
    const uint4* Ahi_p = reinterpret_cast<const uint4*>(g_w2frag) + ((0 * 8 + w) * 16) * 32;
    const uint4* Alo_p = reinterpret_cast<const uint4*>(g_w2frag) + ((1 * 8 + w) * 16) * 32;

#pragma unroll
    for (int p = 0; p < PPB; p++) {
        float C2[2][3][4];
#pragma unroll
        for (int mi = 0; mi < 2; mi++)
#pragma unroll
            for (int nt = 0; nt < 3; nt++)
#pragma unroll
                for (int r = 0; r < 4; r++) C2[mi][nt][r] = 0.f;

#pragma unroll
        for (int ks = 0; ks < 4; ks++) {
            unsigned bh0[3], bh1[3];
#pragma unroll
            for (int nt = 0; nt < 3; nt++) {
                const __nv_bfloat16* bh =
                    s_hbf + (p * 24 + nt * 8 + gr) * HBF_STRIDE + ks * 16 + 2 * gc;
                bh0[nt] = *reinterpret_cast<const unsigned*>(bh);
                bh1[nt] = *reinterpret_cast<const unsigned*>(bh + 8);
            }
#pragma unroll
            for (int mi = 0; mi < 2; mi++) {
                int mt = w * 2 + mi;
                uint4 Ah = W1[((0 * 16 + mt) * 4 + ks) * 32 + lane];
                uint4 Al = W1[((1 * 16 + mt) * 4 + ks) * 32 + lane];
#pragma unroll
                for (int nt = 0; nt < 3; nt++) {
                    mma16816(C2[mi][nt], Ah, bh0[nt], bh1[nt]);
                    mma16816(C2[mi][nt], Al, bh0[nt], bh1[nt]);
                }
            }
        }
        if (p == 0) __syncthreads();   // pe1bf reads done before s_abf overwrite
#pragma unroll
        for (int mi = 0; mi < 2; mi++) {
#pragma unroll
            for (int i = 0; i < 2; i++) {
                int row = (w * 2 + mi) * 16 + gr + i * 8;
                float inv = g_c1inv[row], bias = g_c1bias[row];
#pragma unroll
                for (int nt = 0; nt < 3; nt++) {
#pragma unroll
                    for (int j = 0; j < 2; j++) {
                        float x = fmaxf(fmaf(C2[mi][nt][i * 2 + j], inv, bias), 0.f);
                        int nn = nt * 8 + 2 * gc + j;
                        s_abf[(p * 24 + nn) * ABF_STRIDE + row] = __float2bfloat16_rn(x);
                    }
                }
            }
        }
    }
    __syncthreads();

    // ---- Phase 3: GEMM2 (2-term), ks-outer ----
    float C3[PPB][3][4];
#pragma unroll
    for (int p = 0; p < PPB; p++)
#pragma unroll
        for (int nt = 0; nt < 3; nt++)
#pragma unroll
            for (int r = 0; r < 4; r++) C3[p][nt][r] = 0.f;

#pragma unroll 4
    for (int ks = 0; ks < 16; ks++) {
        uint4 Ah = Ahi_p[ks * 32 + lane];
        uint4 Al = Alo_p[ks * 32 + lane];
#pragma unroll
        for (int p = 0; p < PPB; p++) {
#pragma unroll
            for (int nt = 0; nt < 3; nt++) {
                const __nv_bfloat16* bp =
                    s_abf + (p * 24 + nt * 8 + gr) * ABF_STRIDE + ks * 16 + 2 * gc;
                unsigned b0 = *reinterpret_cast<const unsigned*>(bp);
                unsigned b1 = *reinterpret_cast<const unsigned*>(bp + 8);
                mma16816(C3[p][nt], Ah, b0, b1);
                mma16816(C3[p][nt], Al, b0, b1);
            }
        }
    }

    // ---- epilogue: softmax + aggregate ----
    {
#pragma unroll
        for (int p = 0; p < PPB; p++) {
#pragma unroll
            for (int half = 0; half < 2; half++) {
                int r = w * 16 + gr + half * 8;
                int o = r >> 1;
                float ab = abt[o];
                float vals[6];
                int nvalid = (gc < 2) ? 6 : 4;
#pragma unroll
                for (int nt = 0; nt < 3; nt++)
#pragma unroll
                    for (int j = 0; j < 2; j++)
                        vals[nt * 2 + j] = C3[p][nt][half * 2 + j] + ab;
                float mx = -3.4e38f;
                for (int i = 0; i < nvalid; i++) mx = fmaxf(mx, vals[i]);
                mx = fmaxf(mx, __shfl_xor_sync(0xffffffffu, mx, 1));
                mx = fmaxf(mx, __shfl_xor_sync(0xffffffffu, mx, 2));
                const float* vgr = s_vg + p * DIMC * KNNC + o * KNNC;
                float s = 0.f, ws = 0.f;
                for (int i = 0; i < nvalid; i++) {
                    int nt = i >> 1, j = i & 1;
                    int nb = nt * 8 + 2 * gc + j;
                    float e = __expf(vals[i] - mx);
                    s += e;
                    ws = fmaf(e, vgr[nb], ws);
                }
                s += __shfl_xor_sync(0xffffffffu, s, 1);
                s += __shfl_xor_sync(0xffffffffu, s, 2);
                ws += __shfl_xor_sync(0xffffffffu, ws, 1);
                ws += __shfl_xor_sync(0xffffffffu, ws, 2);
                if (gc == 0) s_agg[p * 128 + (r & 1) * 64 + (r >> 1)] = ws / s;
            }
        }
    }
    __syncthreads();

    // ---- Phase 5: y = we @ agg + be + residual (float4 LDS on s_agg) ----
    {
        int c2 = tid >> 1, rr = tid & 1;
        float accp[PPB];
#pragma unroll
        for (int pp = 0; pp < PPB; pp++) accp[pp] = 0.f;
        const float4* w4 = reinterpret_cast<const float4*>(we + c2 * DIMC);
#pragma unroll 4
        for (int o4 = 0; o4 < DIMC / 4; o4++) {
            float4 ww = w4[o4];
#pragma unroll
            for (int pp = 0; pp < PPB; pp++) {
                const float4 av = *reinterpret_cast<const float4*>(
                    s_agg + pp * 128 + rr * 64 + o4 * 4);
                accp[pp] = fmaf(ww.x, av.x,
                           fmaf(ww.y, av.y,
                           fmaf(ww.z, av.z,
                           fmaf(ww.w, av.w, accp[pp]))));
            }
        }
        float bb = be[c2];
#pragma unroll
        for (int pp = 0; pp < PPB; pp++) {
            out[((size_t)(b * CINC + c2)) * (NPTS * UPF) + 2 * (size_t)(n0 + pp) + rr] =
                accp[pp] + bb + query[(b * CINC + c2) * NPTS + n0 + pp];
        }
    }
}

// ================= launch =================
extern "C" void kernel_launch(void* const* d_in, const int* in_sizes, int n_in,
                              void* d_out, int out_size)
{
    const float* pos1     = (const float*)d_in[0];
    const float* query    = (const float*)d_in[1];
    const float* pos2     = (const float*)d_in[2];
    const float* key_feat = (const float*)d_in[3];
    const float* wq  = (const float*)d_in[4];
    const float* bq  = (const float*)d_in[5];
    const float* wk  = (const float*)d_in[6];
    const float* bk  = (const float*)d_in[7];
    const float* wv  = (const float*)d_in[8];
    const float* bv  = (const float*)d_in[9];
    const float* pw1 = (const float*)d_in[10];
    const float* pb1 = (const float*)d_in[11];
    const float* pg  = (const float*)d_in[12];
    const float* pbt = (const float*)d_in[13];
    const float* pm  = (const float*)d_in[14];
    const float* pv  = (const float*)d_in[15];
    const float* pw2 = (const float*)d_in[16];
    const float* pb2 = (const float*)d_in[17];
    const float* aw1 = (const float*)d_in[18];
    const float* ab1 = (const float*)d_in[19];
    const float* ag  = (const float*)d_in[20];
    const float* abt2= (const float*)d_in[21];
    const float* am  = (const float*)d_in[22];
    const float* av  = (const float*)d_in[23];
    const float* awt = (const float*)d_in[24];
    const float* abt = (const float*)d_in[25];
    const float* we  = (const float*)d_in[26];
    const float* be  = (const float*)d_in[27];
    float* out = (float*)d_out;

    prep_kernel<<<128, 256>>>(aw1, pw2, wq, wk, wv, awt, ab1, ag, abt2, am, av,
                              pw1, pb1, pg, pbt, pm, pv);
    qkv_kernel<<<dim3(NPTS / 64, BATCH), 256>>>(query, key_feat, bq, bk, bv);
    knn_kernel<<<dim3(NPTS / 128, BATCH), 512>>>(pos1, pos2);
    attn_kernel<<<dim3(NPTS / PPB, BATCH), 256>>>(
        pos1, pos2, query, pb2, abt, we, be, out);
}

// round 16
// speedup vs baseline: 1.5433x; 1.5433x over previous
#include <cuda_runtime.h>
#include <cuda_bf16.h>
#include <math.h>
#include <stdint.h>

#define BATCH 4
#define NPTS 4096
#define NPTS2 4096
#define CINC 128
#define DIMC 64
#define KNNC 20
#define UPF 2
#define HPOSC 64
#define HATTC 256
#define EPSV 1e-5f
#define PPB 2
#define ABF_STRIDE 264   // channels stride in s_abf rows
#define HBF_STRIDE 72    // o stride in s_hbf / s_pe1bf rows

// ---------------- scratch ----------------
__device__ float g_qt[BATCH * NPTS * DIMC];
__device__ float g_kt[BATCH * NPTS2 * DIMC];
__device__ float g_vt[BATCH * NPTS2 * DIMC];
__device__ int   g_idx[BATCH * NPTS * KNNC];
__device__ float g_wqt[CINC * DIMC];
__device__ float g_wkt[CINC * DIMC];
__device__ float g_wvt[CINC * DIMC];
__device__ unsigned g_w2frag[2 * 8 * 16 * 32 * 4];
__device__ unsigned g_w1frag[2 * 16 * 4 * 32 * 4];
__device__ unsigned g_pwfrag[2 * 4 * 4 * 32 * 4];
__device__ float g_c1inv[HATTC];
__device__ float g_c1bias[HATTC];
__device__ float g_pw1s[HPOSC * 3];   // pw1 prescaled by BN inv
__device__ float g_pbias[HPOSC];      // fused BN bias for pos layer 1

// ---------------- f32x2 helpers ----------------
__device__ __forceinline__ unsigned long long ffma2(
    unsigned long long a, unsigned long long b, unsigned long long c) {
    unsigned long long d;
    asm("fma.rn.f32x2 %0, %1, %2, %3;" : "=l"(d) : "l"(a), "l"(b), "l"(c));
    return d;
}
__device__ __forceinline__ unsigned long long pack2(float lo, float hi) {
    unsigned long long d;
    asm("mov.b64 %0, {%1, %2};" : "=l"(d) : "f"(lo), "f"(hi));
    return d;
}
__device__ __forceinline__ void unpack2(unsigned long long v, float& lo, float& hi) {
    asm("mov.b64 {%0, %1}, %2;" : "=f"(lo), "=f"(hi) : "l"(v));
}

// ---------------- mma.sync helper ----------------
__device__ __forceinline__ void mma16816(float* c, const uint4& a, unsigned b0, unsigned b1) {
    asm volatile(
        "mma.sync.aligned.m16n8k16.row.col.f32.bf16.bf16.f32 "
        "{%0,%1,%2,%3}, {%4,%5,%6,%7}, {%8,%9}, {%0,%1,%2,%3};"
        : "+f"(c[0]), "+f"(c[1]), "+f"(c[2]), "+f"(c[3])
        : "r"(a.x), "r"(a.y), "r"(a.z), "r"(a.w), "r"(b0), "r"(b1));
}
__device__ __forceinline__ unsigned bfpack(float x0, float x1) {
    return (unsigned)__bfloat16_as_ushort(__float2bfloat16_rn(x0)) |
           ((unsigned)__bfloat16_as_ushort(__float2bfloat16_rn(x1)) << 16);
}

// ================= prep =================
__global__ __launch_bounds__(256) void prep_kernel(
    const float* __restrict__ aw1, const float* __restrict__ pw2,
    const float* __restrict__ wq, const float* __restrict__ wk,
    const float* __restrict__ wv, const float* __restrict__ awt,
    const float* __restrict__ ab1, const float* __restrict__ ag,
    const float* __restrict__ abt2, const float* __restrict__ am,
    const float* __restrict__ av,
    const float* __restrict__ pw1, const float* __restrict__ pb1,
    const float* __restrict__ pg,  const float* __restrict__ pbt,
    const float* __restrict__ pm,  const float* __restrict__ pv)
{
    int i = blockIdx.x * 256 + threadIdx.x;
    if (i < DIMC * CINC) {
        int o = i >> 7, c = i & 127;
        g_wqt[c * DIMC + o] = wq[i];
        g_wkt[c * DIMC + o] = wk[i];
        g_wvt[c * DIMC + o] = wv[i];
    }
    if (i < HATTC) {
        float inv = ag[i] * rsqrtf(av[i] + EPSV);
        g_c1inv[i] = inv;
        g_c1bias[i] = fmaf(ab1[i], inv, abt2[i]) - am[i] * inv;
    }
    if (i < HPOSC) {
        float inv = pg[i] * rsqrtf(pv[i] + EPSV);
        g_pbias[i] = (pb1[i] - pm[i]) * inv + pbt[i];
        g_pw1s[i * 3 + 0] = pw1[i * 3 + 0] * inv;
        g_pw1s[i * 3 + 1] = pw1[i * 3 + 1] * inv;
        g_pw1s[i * 3 + 2] = pw1[i * 3 + 2] * inv;
    }
    if (i < 32768) {                       // W2 A-fragments
        int reg = i & 3, lane = (i >> 2) & 31, ks = (i >> 7) & 15;
        int mt = (i >> 11) & 7, plane = (i >> 14) & 1;
        int gr = lane >> 2, gc = lane & 3;
        int row = mt * 16 + gr + (reg & 1) * 8;
        int col = ks * 16 + 2 * gc + ((reg >> 1) & 1) * 8;
        float x0 = awt[col * 128 + row];
        float x1 = awt[(col + 1) * 128 + row];
        unsigned v;
        if (plane == 0) v = bfpack(x0, x1);
        else {
            float h0 = __bfloat162float(__float2bfloat16_rn(x0));
            float h1 = __bfloat162float(__float2bfloat16_rn(x1));
            v = bfpack(x0 - h0, x1 - h1);
        }
        g_w2frag[i] = v;
    }
    if (i < 16384) {                       // W1 A-fragments
        int reg = i & 3, lane = (i >> 2) & 31, ks = (i >> 7) & 3;
        int mt = (i >> 9) & 15, plane = (i >> 13) & 1;
        int gr = lane >> 2, gc = lane & 3;
        int row = mt * 16 + gr + (reg & 1) * 8;
        int col = ks * 16 + 2 * gc + ((reg >> 1) & 1) * 8;
        float x0 = aw1[row * DIMC + col];
        float x1 = aw1[row * DIMC + col + 1];
        unsigned v;
        if (plane == 0) v = bfpack(x0, x1);
        else {
            float h0 = __bfloat162float(__float2bfloat16_rn(x0));
            float h1 = __bfloat162float(__float2bfloat16_rn(x1));
            v = bfpack(x0 - h0, x1 - h1);
        }
        g_w1frag[i] = v;
    }
    if (i < 4096) {                        // PW2 A-fragments
        int reg = i & 3, lane = (i >> 2) & 31, ks = (i >> 7) & 3;
        int mt = (i >> 9) & 3, plane = (i >> 11) & 1;
        int gr = lane >> 2, gc = lane & 3;
        int row = mt * 16 + gr + (reg & 1) * 8;
        int col = ks * 16 + 2 * gc + ((reg >> 1) & 1) * 8;
        float x0 = pw2[row * HPOSC + col];
        float x1 = pw2[row * HPOSC + col + 1];
        unsigned v;
        if (plane == 0) v = bfpack(x0, x1);
        else {
            float h0 = __bfloat162float(__float2bfloat16_rn(x0));
            float h1 = __bfloat162float(__float2bfloat16_rn(x1));
            v = bfpack(x0 - h0, x1 - h1);
        }
        g_pwfrag[i] = v;
    }
}

// ================= QKV =================
__global__ __launch_bounds__(256) void qkv_kernel(
    const float* __restrict__ query, const float* __restrict__ key_feat,
    const float* __restrict__ bq, const float* __restrict__ bk, const float* __restrict__ bv)
{
    int b = blockIdx.y;
    int n0 = blockIdx.x * 128;
    int tid = threadIdx.x;
    __shared__ __align__(16) float tile[CINC * 128];
    int o = tid & 63, jb = tid >> 6;

    for (int i = tid; i < CINC * 128; i += 256) {
        int c = i >> 7, j = i & 127;
        tile[i] = query[(b * CINC + c) * NPTS + n0 + j];
    }
    __syncthreads();
    {
        unsigned long long acc[16];
#pragma unroll
        for (int m = 0; m < 16; m++) acc[m] = 0ULL;
#pragma unroll 4
        for (int c = 0; c < CINC; c++) {
            float w = g_wqt[c * DIMC + o];
            unsigned long long wp = pack2(w, w);
            const ulonglong2* tp = reinterpret_cast<const ulonglong2*>(tile + c * 128 + jb * 32);
#pragma unroll
            for (int jj = 0; jj < 8; jj++) {
                ulonglong2 t = tp[jj];
                acc[2 * jj]     = ffma2(wp, t.x, acc[2 * jj]);
                acc[2 * jj + 1] = ffma2(wp, t.y, acc[2 * jj + 1]);
            }
        }
        float bias = bq[o];
#pragma unroll
        for (int m = 0; m < 16; m++) {
            float lo, hi;
            unpack2(acc[m], lo, hi);
            int j = jb * 32 + 2 * m;
            g_qt[(b * NPTS + n0 + j) * DIMC + o]     = lo + bias;
            g_qt[(b * NPTS + n0 + j + 1) * DIMC + o] = hi + bias;
        }
    }
    __syncthreads();
    for (int i = tid; i < CINC * 128; i += 256) {
        int c = i >> 7, j = i & 127;
        tile[i] = key_feat[(b * CINC + c) * NPTS2 + n0 + j];
    }
    __syncthreads();
#pragma unroll
    for (int which = 0; which < 2; which++) {
        const float* wt = which ? g_wvt : g_wkt;
        float* gout = which ? g_vt : g_kt;
        float bias = which ? bv[o] : bk[o];
        unsigned long long acc[16];
#pragma unroll
        for (int m = 0; m < 16; m++) acc[m] = 0ULL;
#pragma unroll 4
        for (int c = 0; c < CINC; c++) {
            float w = wt[c * DIMC + o];
            unsigned long long wp = pack2(w, w);
            const ulonglong2* tp = reinterpret_cast<const ulonglong2*>(tile + c * 128 + jb * 32);
#pragma unroll
            for (int jj = 0; jj < 8; jj++) {
                ulonglong2 t = tp[jj];
                acc[2 * jj]     = ffma2(wp, t.x, acc[2 * jj]);
                acc[2 * jj + 1] = ffma2(wp, t.y, acc[2 * jj + 1]);
            }
        }
#pragma unroll
        for (int m = 0; m < 16; m++) {
            float lo, hi;
            unpack2(acc[m], lo, hi);
            int j = jb * 32 + 2 * m;
            gout[(b * NPTS2 + n0 + j) * DIMC + o]     = lo + bias;
            gout[(b * NPTS2 + n0 + j + 1) * DIMC + o] = hi + bias;
        }
    }
}

// ================= KNN =================
#define INSERT_CHAIN(d_, i_) do { \
    float cd = (d_); int ci = (i_); \
    _Pragma("unroll") \
    for (int j = 0; j < KNNC; j++) { \
        if (cd < bd[j]) { \
            float td = bd[j]; bd[j] = cd; cd = td; \
            int ti = bi[j]; bi[j] = ci; ci = ti; \
        } \
    } \
} while (0)

__global__ __launch_bounds__(512) void knn_kernel(
    const float* __restrict__ pos1, const float* __restrict__ pos2)
{
    int b = blockIdx.y;
    int tid = threadIdx.x;
    int q = tid & 127, quarter = tid >> 7;
    int n = blockIdx.x * 128 + q;

    __shared__ float sx[4096], sy[4096], sz[4096], sq2[4096];  // 64 KB
    __shared__ float smd[512][KNNC];                           // 40 KB
    __shared__ int   smi[512][KNNC];                           // 40 KB
    __shared__ float sbd[512][13];                             // 26 KB (stride 13: conflict-free)
    __shared__ int   sbi[512][13];                             // 26 KB

    for (int i = tid; i < 4096; i += 512) {
        float x = pos2[(b * 3 + 0) * NPTS2 + i];
        float y = pos2[(b * 3 + 1) * NPTS2 + i];
        float z = pos2[(b * 3 + 2) * NPTS2 + i];
        sx[i] = x; sy[i] = y; sz[i] = z;
        sq2[i] = x * x + y * y + z * z;
    }
    float qx = pos1[(b * 3 + 0) * NPTS + n];
    float qy = pos1[(b * 3 + 1) * NPTS + n];
    float qz = pos1[(b * 3 + 2) * NPTS + n];
    float n1 = qx * qx + qy * qy + qz * qz;

    float bd[KNNC];
    int bi[KNNC];
#pragma unroll
    for (int j = 0; j < KNNC; j++) { bd[j] = 3.4e38f; bi[j] = 0; }
    __syncthreads();
    int base = quarter * 1024;

    for (int m = 0; m < 64; m++) {
        int mm = base + m;
        float dot = fmaf(qx, sx[mm], fmaf(qy, sy[mm], qz * sz[mm]));
        float d = n1 + sq2[mm] - 2.f * dot;
        if (d < bd[KNNC - 1]) INSERT_CHAIN(d, mm);
    }
    for (int chunk = 0; chunk < 15; chunk++) {
        int s0 = 64 + chunk * 64;
        float thr = bd[KNNC - 1];
        int cnt = 0;
        for (int m = s0; m < s0 + 64; m++) {
            int mm = base + m;
            float dot = fmaf(qx, sx[mm], fmaf(qy, sy[mm], qz * sz[mm]));
            float d = n1 + sq2[mm] - 2.f * dot;
            if (d < thr) {
                if (cnt < 13) { sbd[tid][cnt] = d; sbi[tid][cnt] = mm; cnt++; }
                else if (d < bd[KNNC - 1]) INSERT_CHAIN(d, mm);
            }
        }
        for (int t = 0; t < cnt; t++) {
            float d = sbd[tid][t];
            int mm = sbi[tid][t];
            if (d < bd[KNNC - 1]) INSERT_CHAIN(d, mm);
        }
    }
#pragma unroll
    for (int j = 0; j < KNNC; j++) { smd[tid][j] = bd[j]; smi[tid][j] = bi[j]; }
    __syncthreads();
    if (quarter == 0) {
        int head[4] = {0, 0, 0, 0};
#pragma unroll
        for (int t = 0; t < KNNC; t++) {
            float best = 3.5e38f;
            int bqv = 0;
#pragma unroll
            for (int qu = 0; qu < 4; qu++) {
                if (head[qu] < KNNC) {
                    float v = smd[qu * 128 + q][head[qu]];
                    if (v < best) { best = v; bqv = qu; }
                }
            }
            g_idx[(b * NPTS + n) * KNNC + t] = smi[bqv * 128 + q][head[bqv]];
            head[bqv]++;
        }
    }
}

// ================= fused attention kernel =================
__global__ __launch_bounds__(256, 4) void attn_kernel(
    const float* __restrict__ pos1, const float* __restrict__ pos2,
    const float* __restrict__ query,
    const float* __restrict__ pb2,
    const float* __restrict__ abt,
    const float* __restrict__ we,  const float* __restrict__ be,
    float* __restrict__ out)
{
    int b = blockIdx.y;
    int n0 = blockIdx.x * PPB;
    int tid = threadIdx.x;

    __shared__ __align__(16) float s_h[PPB * DIMC * KNNC];
    __shared__ __align__(16) float s_vg[PPB * DIMC * KNNC];
    __shared__ __align__(16) unsigned char s_big[PPB * 24 * ABF_STRIDE * 2];
    __shared__ __align__(16) __nv_bfloat16 s_hbf[PPB * 24 * HBF_STRIDE];
    __shared__ float s_q[PPB * DIMC];
    __shared__ float s_prel[PPB * 3 * KNNC];
    __shared__ __align__(16) float s_agg[PPB * DIMC * UPF];   // [p][rr*64+o]
    __shared__ int   s_idx[PPB * KNNC];

    __nv_bfloat16* s_pe1bf = reinterpret_cast<__nv_bfloat16*>(s_big);
    __nv_bfloat16* s_abf = reinterpret_cast<__nv_bfloat16*>(s_big);

    // ---- Phase 0 ----
    if (tid < PPB * KNNC) {
        int p = tid / KNNC, k = tid - p * KNNC;
        s_idx[tid] = g_idx[(b * NPTS + n0 + p) * KNNC + k];
    }
    if (tid < PPB * DIMC) {
        int p = tid >> 6, o = tid & 63;
        s_q[tid] = g_qt[(b * NPTS + n0 + p) * DIMC + o];
    }
    {
        unsigned* hz = reinterpret_cast<unsigned*>(s_hbf);
        for (int e = tid; e < PPB * 4 * (HBF_STRIDE / 2); e += 256) {
            int woff = e % (HBF_STRIDE / 2);
            int rsel = e / (HBF_STRIDE / 2);
            int r = rsel & 3, p = rsel >> 2;
            hz[(p * 24 + 20 + r) * (HBF_STRIDE / 2) + woff] = 0u;
        }
    }
    __syncthreads();
    if (tid < PPB * 3 * KNNC) {
        int p = tid / (3 * KNNC), rem = tid - p * 3 * KNNC;
        int c = rem / KNNC, k = rem - c * KNNC;
        s_prel[tid] = pos1[(b * 3 + c) * NPTS + n0 + p]
                    - pos2[(b * 3 + c) * NPTS2 + s_idx[p * KNNC + k]];
    }
#pragma unroll
    for (int p = 0; p < PPB; p++) {
        for (int e = tid; e < DIMC * KNNC / 4; e += 256) {   // 320 float4 groups
            int k = e >> 4, o4 = e & 15;
            int m = s_idx[p * KNNC + k];
            const float4 kv = *reinterpret_cast<const float4*>(
                g_kt + ((size_t)(b * NPTS2 + m)) * DIMC + o4 * 4);
            const float4 vv = *reinterpret_cast<const float4*>(
                g_vt + ((size_t)(b * NPTS2 + m)) * DIMC + o4 * 4);
            const float4 qv = *reinterpret_cast<const float4*>(s_q + p * DIMC + o4 * 4);
            float* hb = s_h + p * DIMC * KNNC;
            float* vb = s_vg + p * DIMC * KNNC;
            int o = o4 * 4;
            hb[(o + 0) * KNNC + k] = qv.x - kv.x;
            hb[(o + 1) * KNNC + k] = qv.y - kv.y;
            hb[(o + 2) * KNNC + k] = qv.z - kv.z;
            hb[(o + 3) * KNNC + k] = qv.w - kv.w;
            vb[(o + 0) * KNNC + k] = vv.x;
            vb[(o + 1) * KNNC + k] = vv.y;
            vb[(o + 2) * KNNC + k] = vv.z;
            vb[(o + 3) * KNNC + k] = vv.w;
        }
    }
    __syncthreads();

    // ---- Phase 1: pe1 = relu(pw1s @ prel + pbias) -> s_pe1bf bf16 [k][h] ----
    for (int e = tid; e < PPB * 24 * 32; e += 256) {
        int hp = e & 31;
        int rem = e >> 5;
        int k = rem % 24, p = rem / 24;
        float v0 = 0.f, v1 = 0.f;
        if (k < KNNC) {
            const float* pr = s_prel + p * 3 * KNNC;
            float x = pr[k], y = pr[KNNC + k], z = pr[2 * KNNC + k];
            int h0 = 2 * hp, h1 = 2 * hp + 1;
            v0 = fmaxf(fmaf(g_pw1s[h0 * 3], x,
                       fmaf(g_pw1s[h0 * 3 + 1], y,
                       fmaf(g_pw1s[h0 * 3 + 2], z, g_pbias[h0]))), 0.f);
            v1 = fmaxf(fmaf(g_pw1s[h1 * 3], x,
                       fmaf(g_pw1s[h1 * 3 + 1], y,
                       fmaf(g_pw1s[h1 * 3 + 2], z, g_pbias[h1]))), 0.f);
        }
        unsigned* w0 = reinterpret_cast<unsigned*>(s_pe1bf);
        w0[(p * 24 + k) * (HBF_STRIDE / 2) + hp] = bfpack(v0, v1);
    }
    __syncthreads();

    // ---- Phase 1b: pe = pw2 @ pe1 (2-term mma); fold into s_hbf and s_vg ----
    int w = tid >> 5, lane = tid & 31;
    int gr = lane >> 2, gc = lane & 3;
    {
        int p1 = w >> 2, mt = w & 3;
        float Cpe[3][4];
#pragma unroll
        for (int nt = 0; nt < 3; nt++)
#pragma unroll
            for (int r = 0; r < 4; r++) Cpe[nt][r] = 0.f;
        const uint4* PW = reinterpret_cast<const uint4*>(g_pwfrag);
#pragma unroll
        for (int ks = 0; ks < 4; ks++) {
            uint4 Ah = PW[((0 * 4 + mt) * 4 + ks) * 32 + lane];
            uint4 Al = PW[((1 * 4 + mt) * 4 + ks) * 32 + lane];
#pragma unroll
            for (int nt = 0; nt < 3; nt++) {
                const __nv_bfloat16* bh =
                    s_pe1bf + (p1 * 24 + nt * 8 + gr) * HBF_STRIDE + ks * 16 + 2 * gc;
                unsigned b0 = *reinterpret_cast<const unsigned*>(bh);
                unsigned b1 = *reinterpret_cast<const unsigned*>(bh + 8);
                mma16816(Cpe[nt], Ah, b0, b1);
                mma16816(Cpe[nt], Al, b0, b1);
            }
        }
#pragma unroll
        for (int nt = 0; nt < 3; nt++) {
#pragma unroll
            for (int i = 0; i < 2; i++) {
#pragma unroll
                for (int j = 0; j < 2; j++) {
                    int row = mt * 16 + gr + i * 8;
                    int nb = nt * 8 + 2 * gc + j;
                    if (nb < KNNC) {
                        float val = Cpe[nt][i * 2 + j] + pb2[row];
                        int off = p1 * DIMC * KNNC + row * KNNC + nb;
                        float hv = s_h[off] + val;
                        s_vg[off] += val;
                        s_hbf[(p1 * 24 + nb) * HBF_STRIDE + row] = __float2bfloat16_rn(hv);
                    }
                }
            }
        }
    }
    __syncthreads();

    // ---- Phase 2: GEMM1 (2-term mma) both points -> s_abf ----
    const uint4* W1 = reinterpret_cast<const uint4*>(g_w1frag);
    const uint4* Ahi_p = reinterpret_cast<const uint4*>(g_w2frag) + ((0 * 8 + w) * 16) * 32;
    const uint4* Alo_p = reinterpret_cast<const uint4*>(g_w2frag) + ((1 * 8 + w) * 16) * 32;

#pragma unroll
    for (int p = 0; p < PPB; p++) {
        float C2[2][3][4];
#pragma unroll
        for (int mi = 0; mi < 2; mi++)
#pragma unroll
            for (int nt = 0; nt < 3; nt++)
#pragma unroll
                for (int r = 0; r < 4; r++) C2[mi][nt][r] = 0.f;

#pragma unroll
        for (int ks = 0; ks < 4; ks++) {
            unsigned bh0[3], bh1[3];
#pragma unroll
            for (int nt = 0; nt < 3; nt++) {
                const __nv_bfloat16* bh =
                    s_hbf + (p * 24 + nt * 8 + gr) * HBF_STRIDE + ks * 16 + 2 * gc;
                bh0[nt] = *reinterpret_cast<const unsigned*>(bh);
                bh1[nt] = *reinterpret_cast<const unsigned*>(bh + 8);
            }
#pragma unroll
            for (int mi = 0; mi < 2; mi++) {
                int mt = w * 2 + mi;
                uint4 Ah = W1[((0 * 16 + mt) * 4 + ks) * 32 + lane];
                uint4 Al = W1[((1 * 16 + mt) * 4 + ks) * 32 + lane];
#pragma unroll
                for (int nt = 0; nt < 3; nt++) {
                    mma16816(C2[mi][nt], Ah, bh0[nt], bh1[nt]);
                    mma16816(C2[mi][nt], Al, bh0[nt], bh1[nt]);
                }
            }
        }
        if (p == 0) __syncthreads();   // pe1bf reads done before s_abf overwrite
#pragma unroll
        for (int mi = 0; mi < 2; mi++) {
#pragma unroll
            for (int i = 0; i < 2; i++) {
                int row = (w * 2 + mi) * 16 + gr + i * 8;
                float inv = g_c1inv[row], bias = g_c1bias[row];
#pragma unroll
                for (int nt = 0; nt < 3; nt++) {
#pragma unroll
                    for (int j = 0; j < 2; j++) {
                        float x = fmaxf(fmaf(C2[mi][nt][i * 2 + j], inv, bias), 0.f);
                        int nn = nt * 8 + 2 * gc + j;
                        s_abf[(p * 24 + nn) * ABF_STRIDE + row] = __float2bfloat16_rn(x);
                    }
                }
            }
        }
    }
    __syncthreads();

    // ---- Phase 3: GEMM2 (2-term), ks-outer ----
    float C3[PPB][3][4];
#pragma unroll
    for (int p = 0; p < PPB; p++)
#pragma unroll
        for (int nt = 0; nt < 3; nt++)
#pragma unroll
            for (int r = 0; r < 4; r++) C3[p][nt][r] = 0.f;

#pragma unroll 4
    for (int ks = 0; ks < 16; ks++) {
        uint4 Ah = Ahi_p[ks * 32 + lane];
        uint4 Al = Alo_p[ks * 32 + lane];
#pragma unroll
        for (int p = 0; p < PPB; p++) {
#pragma unroll
            for (int nt = 0; nt < 3; nt++) {
                const __nv_bfloat16* bp =
                    s_abf + (p * 24 + nt * 8 + gr) * ABF_STRIDE + ks * 16 + 2 * gc;
                unsigned b0 = *reinterpret_cast<const unsigned*>(bp);
                unsigned b1 = *reinterpret_cast<const unsigned*>(bp + 8);
                mma16816(C3[p][nt], Ah, b0, b1);
                mma16816(C3[p][nt], Al, b0, b1);
            }
        }
    }

    // ---- epilogue: softmax + aggregate ----
    {
#pragma unroll
        for (int p = 0; p < PPB; p++) {
#pragma unroll
            for (int half = 0; half < 2; half++) {
                int r = w * 16 + gr + half * 8;
                int o = r >> 1;
                float ab = abt[o];
                float vals[6];
                int nvalid = (gc < 2) ? 6 : 4;
#pragma unroll
                for (int nt = 0; nt < 3; nt++)
#pragma unroll
                    for (int j = 0; j < 2; j++)
                        vals[nt * 2 + j] = C3[p][nt][half * 2 + j] + ab;
                float mx = -3.4e38f;
                for (int i = 0; i < nvalid; i++) mx = fmaxf(mx, vals[i]);
                mx = fmaxf(mx, __shfl_xor_sync(0xffffffffu, mx, 1));
                mx = fmaxf(mx, __shfl_xor_sync(0xffffffffu, mx, 2));
                const float* vgr = s_vg + p * DIMC * KNNC + o * KNNC;
                float s = 0.f, ws = 0.f;
                for (int i = 0; i < nvalid; i++) {
                    int nt = i >> 1, j = i & 1;
                    int nb = nt * 8 + 2 * gc + j;
                    float e = __expf(vals[i] - mx);
                    s += e;
                    ws = fmaf(e, vgr[nb], ws);
                }
                s += __shfl_xor_sync(0xffffffffu, s, 1);
                s += __shfl_xor_sync(0xffffffffu, s, 2);
                ws += __shfl_xor_sync(0xffffffffu, ws, 1);
                ws += __shfl_xor_sync(0xffffffffu, ws, 2);
                if (gc == 0) s_agg[p * 128 + (r & 1) * 64 + (r >> 1)] = ws / s;
            }
        }
    }
    __syncthreads();

    // ---- Phase 5: y = we @ agg + be + residual (float4 LDS on s_agg) ----
    {
        int c2 = tid >> 1, rr = tid & 1;
        float accp[PPB];
#pragma unroll
        for (int pp = 0; pp < PPB; pp++) accp[pp] = 0.f;
        const float4* w4 = reinterpret_cast<const float4*>(we + c2 * DIMC);
#pragma unroll 4
        for (int o4 = 0; o4 < DIMC / 4; o4++) {
            float4 ww = w4[o4];
#pragma unroll
            for (int pp = 0; pp < PPB; pp++) {
                const float4 av = *reinterpret_cast<const float4*>(
                    s_agg + pp * 128 + rr * 64 + o4 * 4);
                accp[pp] = fmaf(ww.x, av.x,
                           fmaf(ww.y, av.y,
                           fmaf(ww.z, av.z,
                           fmaf(ww.w, av.w, accp[pp]))));
            }
        }
        float bb = be[c2];
#pragma unroll
        for (int pp = 0; pp < PPB; pp++) {
            out[((size_t)(b * CINC + c2)) * (NPTS * UPF) + 2 * (size_t)(n0 + pp) + rr] =
                accp[pp] + bb + query[(b * CINC + c2) * NPTS + n0 + pp];
        }
    }
}

// ================= launch =================
extern "C" void kernel_launch(void* const* d_in, const int* in_sizes, int n_in,
                              void* d_out, int out_size)
{
    const float* pos1     = (const float*)d_in[0];
    const float* query    = (const float*)d_in[1];
    const float* pos2     = (const float*)d_in[2];
    const float* key_feat = (const float*)d_in[3];
    const float* wq  = (const float*)d_in[4];
    const float* bq  = (const float*)d_in[5];
    const float* wk  = (const float*)d_in[6];
    const float* bk  = (const float*)d_in[7];
    const float* wv  = (const float*)d_in[8];
    const float* bv  = (const float*)d_in[9];
    const float* pw1 = (const float*)d_in[10];
    const float* pb1 = (const float*)d_in[11];
    const float* pg  = (const float*)d_in[12];
    const float* pbt = (const float*)d_in[13];
    const float* pm  = (const float*)d_in[14];
    const float* pv  = (const float*)d_in[15];
    const float* pw2 = (const float*)d_in[16];
    const float* pb2 = (const float*)d_in[17];
    const float* aw1 = (const float*)d_in[18];
    const float* ab1 = (const float*)d_in[19];
    const float* ag  = (const float*)d_in[20];
    const float* abt2= (const float*)d_in[21];
    const float* am  = (const float*)d_in[22];
    const float* av  = (const float*)d_in[23];
    const float* awt = (const float*)d_in[24];
    const float* abt = (const float*)d_in[25];
    const float* we  = (const float*)d_in[26];
    const float* be  = (const float*)d_in[27];
    float* out = (float*)d_out;

    prep_kernel<<<128, 256>>>(aw1, pw2, wq, wk, wv, awt, ab1, ag, abt2, am, av,
                              pw1, pb1, pg, pbt, pm, pv);
    qkv_kernel<<<dim3(NPTS / 128, BATCH), 256>>>(query, key_feat, bq, bk, bv);
    knn_kernel<<<dim3(NPTS / 128, BATCH), 512>>>(pos1, pos2);
    attn_kernel<<<dim3(NPTS / PPB, BATCH), 256>>>(
        pos1, pos2, query, pb2, abt, we, be, out);
}